// round 14
// baseline (speedup 1.0000x reference)
#include <cuda_runtime.h>
#include <cuda_bf16.h>

// Problem constants
#define BB    64
#define SS    4096
#define LL    25
#define NBINS 3600         // 60*60
#define CAPC  128
#define NBAND 12           // 12 bands of 5 output rows (a 5x5 window spans <=2)
#define BPB   300          // bins per band (5*60)
#define NC2   64           // chunks per batch
#define CH2   (SS / NC2)   // 64 spikes per chunk
#define NT    (BB * NBAND) // 768 (b,band) tiles
#define FULLM 0xffffffffu

#define BUILD_SMEM (CAPC * BPB * 4 + NC2 * BPB * 2)   // 153600 + 38400 = 192000

// Scratch (static device globals)
__device__ unsigned int g_cnt[NT * NC2];    // events per (tile, chunk)
__device__ unsigned int g_choff[NT * NC2];  // exclusive chunk offsets within tile
__device__ unsigned int g_base[NT];         // tile base into g_ev
__device__ int g_ev[BB * SS * LL];          // packed events (j), 26.2 MB

// ---------------------------------------------------------------------------
// K1: count events per (b,band,chunk). Warp per (b,chunk of 64 spikes).
// Depth-8 pipelined gathers; counting via shared atomics (order irrelevant).
// ---------------------------------------------------------------------------
__global__ void count_kernel(const int* __restrict__ spikes,
                             const int* __restrict__ indices) {
    __shared__ unsigned int wc[4][NBAND];
    int warp = threadIdx.x >> 5, lane = threadIdx.x & 31;
    int w = blockIdx.x * 4 + warp;
    int b = w >> 6, c = w & 63;
    if (lane < NBAND) wc[warp][lane] = 0;
    const int* sp = spikes + b * SS + c * CH2;
    int idlo = __ldg(&sp[lane]);
    int idhi = __ldg(&sp[32 + lane]);
    bool act = lane < LL;
    __syncwarp();

    #define GATHER(dst, s) do {                                              \
        int _id = ((s) < 32) ? __shfl_sync(FULLM, idlo, (s))                 \
                             : __shfl_sync(FULLM, idhi, (s) - 32);           \
        (dst) = act ? __ldg(&indices[_id * LL + lane]) : -1;                 \
    } while (0)

    #define PROC(jv) do {                                                    \
        if ((jv) >= 0) {                                                     \
            unsigned int ju = (unsigned int)(jv);                            \
            unsigned int band = (ju % NBINS) / BPB;                          \
            atomicAdd(&wc[warp][band], 1u);                                  \
        }                                                                    \
    } while (0)

    int a0, a1, a2, a3, b0, b1, b2, b3;
    GATHER(a0, 0); GATHER(a1, 1); GATHER(a2, 2); GATHER(a3, 3);
    GATHER(b0, 4); GATHER(b1, 5); GATHER(b2, 6); GATHER(b3, 7);
    #pragma unroll 2
    for (int g = 0; g < CH2 / 4 - 2; g++) {
        int s = g * 4;
        int c0, c1, c2, c3;
        GATHER(c0, s + 8); GATHER(c1, s + 9); GATHER(c2, s + 10); GATHER(c3, s + 11);
        PROC(a0); PROC(a1); PROC(a2); PROC(a3);
        a0 = b0; a1 = b1; a2 = b2; a3 = b3;
        b0 = c0; b1 = c1; b2 = c2; b3 = c3;
    }
    PROC(a0); PROC(a1); PROC(a2); PROC(a3);
    PROC(b0); PROC(b1); PROC(b2); PROC(b3);
    #undef GATHER
    #undef PROC

    __syncwarp();
    if (lane < NBAND)
        g_cnt[(b * NBAND + lane) * NC2 + c] = wc[warp][lane];
}

// ---------------------------------------------------------------------------
// K2: exact offsets. One block, 768 threads (one per tile). uint4-batched
// loads give ILP=16 (R11's version did 64 serial dependent LDGs -> ~20us).
// ---------------------------------------------------------------------------
__global__ void scan_kernel2() {
    __shared__ unsigned int wsum[24];
    int t = threadIdx.x;               // 0..767
    int lane = t & 31, wid = t >> 5;   // 24 warps

    uint4 v[16];
    const uint4* src = (const uint4*)(g_cnt + t * NC2);
    #pragma unroll
    for (int i = 0; i < 16; i++) v[i] = __ldg(&src[i]);

    unsigned int sum = 0;
    uint4* dst = (uint4*)(g_choff + t * NC2);
    #pragma unroll
    for (int i = 0; i < 16; i++) {
        uint4 o;
        o.x = sum; sum += v[i].x;
        o.y = sum; sum += v[i].y;
        o.z = sum; sum += v[i].z;
        o.w = sum; sum += v[i].w;
        dst[i] = o;
    }

    unsigned int mytot = sum;
    unsigned int s1 = mytot;
    #pragma unroll
    for (int d = 1; d < 32; d <<= 1) {
        unsigned int x = __shfl_up_sync(FULLM, s1, d);
        if (lane >= d) s1 += x;
    }
    if (lane == 31) wsum[wid] = s1;
    __syncthreads();
    if (wid == 0) {
        unsigned int s = (lane < 24) ? wsum[lane] : 0;
        #pragma unroll
        for (int d = 1; d < 32; d <<= 1) {
            unsigned int x = __shfl_up_sync(FULLM, s, d);
            if (lane >= d) s += x;
        }
        if (lane < 24) wsum[lane] = s;
    }
    __syncthreads();
    g_base[t] = s1 - mytot + (wid ? wsum[wid - 1] : 0u);
}

// ---------------------------------------------------------------------------
// K3: place events into packed buckets in (s,l) order, SPLIT BY BAND PARITY.
// Warp per (b,chunk,parity): walks all 64 spikes, handles only bands of its
// parity (each band owned by exactly one warp -> ordering preserved).
// 8192 warps (~80% occ). Writes coalesced within band groups.
// ---------------------------------------------------------------------------
__global__ void place_kernel(const int* __restrict__ spikes,
                             const int* __restrict__ indices) {
    __shared__ unsigned int eb[8][NBAND];
    int warp = threadIdx.x >> 5, lane = threadIdx.x & 31;
    int task = blockIdx.x * 8 + warp;     // 8192
    int w = task >> 1;
    unsigned int par = task & 1;
    int b = w >> 6, c = w & 63;
    if (lane < NBAND) {
        int t = b * NBAND + lane;
        eb[warp][lane] = g_base[t] + g_choff[t * NC2 + c];
    }
    const int* sp = spikes + b * SS + c * CH2;
    int idlo = __ldg(&sp[lane]);
    int idhi = __ldg(&sp[32 + lane]);
    bool act = lane < LL;
    unsigned int ltm = (1u << lane) - 1u;
    __syncwarp();

    #define GATHER(dst, s) do {                                              \
        int _id = ((s) < 32) ? __shfl_sync(FULLM, idlo, (s))                 \
                             : __shfl_sync(FULLM, idhi, (s) - 32);           \
        (dst) = act ? __ldg(&indices[_id * LL + lane]) : -1;                 \
    } while (0)

    #define PROC(jv) do {                                                    \
        unsigned int ju = (unsigned int)(jv);                                \
        unsigned int band = ((jv) >= 0) ? (ju % NBINS) / BPB : (32u + lane); \
        bool valid = ((jv) >= 0) && ((band & 1u) == par);                    \
        if (!valid) band = 32u + lane;                                       \
        unsigned int peers = __match_any_sync(FULLM, band);                  \
        unsigned int rank = __popc(peers & ltm);                             \
        unsigned int base = valid ? eb[warp][band] : 0u;                     \
        __syncwarp();                                                        \
        if (valid && lane == (unsigned)(__ffs(peers) - 1))                   \
            eb[warp][band] = base + __popc(peers);                           \
        __syncwarp();                                                        \
        if (valid) g_ev[base + rank] = (int)ju;                              \
    } while (0)

    int a0, a1, a2, a3, b0, b1, b2, b3;
    GATHER(a0, 0); GATHER(a1, 1); GATHER(a2, 2); GATHER(a3, 3);
    GATHER(b0, 4); GATHER(b1, 5); GATHER(b2, 6); GATHER(b3, 7);
    #pragma unroll 2
    for (int g = 0; g < CH2 / 4 - 2; g++) {
        int s = g * 4;
        int c0, c1, c2, c3;
        GATHER(c0, s + 8); GATHER(c1, s + 9); GATHER(c2, s + 10); GATHER(c3, s + 11);
        PROC(a0); PROC(a1); PROC(a2); PROC(a3);
        a0 = b0; a1 = b1; a2 = b2; a3 = b3;
        b0 = c0; b1 = c1; b2 = c2; b3 = c3;
    }
    PROC(a0); PROC(a1); PROC(a2); PROC(a3);
    PROC(b0); PROC(b1); PROC(b2); PROC(b3);
    #undef GATHER
    #undef PROC
}

// ---------------------------------------------------------------------------
// K4: build. Block (1024 thr = 32 warps) per (b,band) tile. Smem: slab
// float[128][300] + cnt16[64][300]. Phase1: per-chunk bin histogram with
// depth-2 prefetched event loads. Phase2: per-bin exclusive scan over chunks.
// Phase4: warps replay chunks (warp-serial per chunk => order), prefetched
// loads, match_any ranks; slab writes smem-only. Phase5: coalesced stream-out.
// ---------------------------------------------------------------------------
__global__ void build_kernel(float* __restrict__ out) {
    extern __shared__ unsigned char smem[];
    float* slab = (float*)smem;                                   // 153600 B
    unsigned int* cnt32 = (unsigned int*)(smem + CAPC * BPB * 4); // 64*150 u32
    unsigned short* cnt16 = (unsigned short*)cnt32;

    int tile = blockIdx.x;
    int b = tile / NBAND, band = tile % NBAND;
    int tid = threadIdx.x;                 // 1024
    int lane = tid & 31, warp = tid >> 5;  // 32 warps
    unsigned int ltm = (1u << lane) - 1u;

    for (int i = tid; i < NC2 * (BPB / 2); i += 1024) cnt32[i] = 0u;
    float4* s4 = (float4*)slab;
    float4 neg1 = make_float4(-1.0f, -1.0f, -1.0f, -1.0f);
    for (int i = tid; i < CAPC * BPB / 4; i += 1024) s4[i] = neg1;
    __syncthreads();

    unsigned int tb = g_base[tile];

    // Phase 1: histogram per (chunk, bin), depth-2 prefetch on event loads.
    #pragma unroll
    for (int cc = 0; cc < 2; cc++) {
        int c = warp + cc * 32;
        unsigned int start = tb + g_choff[tile * NC2 + c];
        unsigned int n = g_cnt[tile * NC2 + c];
        unsigned int k = lane;
        bool v = k < n;
        unsigned int ju = v ? (unsigned int)__ldg(&g_ev[start + k]) : 0u;
        for (unsigned int k0 = 0; k0 < n; k0 += 32) {
            unsigned int kn = k + 32;
            bool vn = kn < n;
            unsigned int jn = vn ? (unsigned int)__ldg(&g_ev[start + kn]) : 0u;
            if (v) {
                unsigned int binl = (ju % NBINS) - band * BPB;
                atomicAdd(&cnt32[c * (BPB / 2) + (binl >> 1)],
                          1u << (16 * (binl & 1)));
            }
            k = kn; ju = jn; v = vn;
        }
    }
    __syncthreads();

    // Phase 2: exclusive scan over chunks per bin (300 threads).
    if (tid < BPB) {
        unsigned int sum = 0;
        #pragma unroll 8
        for (int c = 0; c < NC2; c++) {
            unsigned int v = cnt16[c * BPB + tid];
            cnt16[c * BPB + tid] = (unsigned short)sum;
            sum += v;
        }
    }
    __syncthreads();

    // Phase 4: ordered local scatter into slab, prefetched loads.
    #pragma unroll
    for (int cc = 0; cc < 2; cc++) {
        int c = warp + cc * 32;
        unsigned int start = tb + g_choff[tile * NC2 + c];
        unsigned int n = g_cnt[tile * NC2 + c];
        unsigned int k = lane;
        bool v = k < n;
        unsigned int ju = v ? (unsigned int)__ldg(&g_ev[start + k]) : 0u;
        for (unsigned int k0 = 0; k0 < n; k0 += 32) {
            unsigned int kn = k + 32;
            bool vn = kn < n;
            unsigned int jn = vn ? (unsigned int)__ldg(&g_ev[start + kn]) : 0u;

            unsigned int binl = v ? (ju % NBINS) - band * BPB : (1000u + lane);
            unsigned int peers = __match_any_sync(FULLM, binl);
            unsigned int rank = __popc(peers & ltm);
            unsigned int base = v ? (unsigned int)cnt16[c * BPB + binl] : 0u;
            __syncwarp();
            if (v && lane == (unsigned)(__ffs(peers) - 1))
                cnt16[c * BPB + binl] = (unsigned short)(base + __popc(peers));
            __syncwarp();
            unsigned int r = base + rank;
            if (v && r < CAPC)
                slab[r * BPB + binl] = (float)(ju / NBINS);

            k = kn; ju = jn; v = vn;
        }
    }
    __syncthreads();

    // Phase 5: stream slab -> out[b, r, band*300 .. +300), coalesced.
    float4* o4 = (float4*)out;
    for (int i = tid; i < CAPC * BPB / 4; i += 1024) {
        int r = i / (BPB / 4), i4 = i % (BPB / 4);
        o4[(size_t)(b * CAPC + r) * (NBINS / 4) + band * (BPB / 4) + i4] = s4[i];
    }
}

// ---------------------------------------------------------------------------
extern "C" void kernel_launch(void* const* d_in, const int* in_sizes, int n_in,
                              void* d_out, int out_size) {
    const int* spikes  = (const int*)d_in[0];   // (64, 4096, 1, 1) int32
    const int* indices = (const int*)d_in[1];   // (131072, 25) int32
    float* out = (float*)d_out;                 // (64, 128, 60, 60) float32

    static bool attr_done = false;
    if (!attr_done) {
        cudaFuncSetAttribute(build_kernel,
                             cudaFuncAttributeMaxDynamicSharedMemorySize,
                             BUILD_SMEM);
        attr_done = true;
    }

    count_kernel<<<BB * NC2 / 4, 128>>>(spikes, indices);
    scan_kernel2<<<1, NT>>>();
    place_kernel<<<BB * NC2 * 2 / 8, 256>>>(spikes, indices);
    build_kernel<<<NT, 1024, BUILD_SMEM>>>(out);
}

// round 15
// speedup vs baseline: 2.7693x; 2.7693x over previous
#include <cuda_runtime.h>
#include <cuda_bf16.h>

// Problem constants (fixed by the dataset builder)
#define BB    64          // batches
#define SS    4096        // spikes per batch
#define LL    25          // Lmax
#define NBINS 3600        // OH*OW
#define CAPC  128         // cap
#define NC    64          // chunks per batch
#define CHUNK (SS / NC)   // 64 spikes per chunk
#define NSC   16          // superchunks of 256 spikes (4 chunks) for packed count
#define OFFCLAMP 160u     // offsets >= 128 are dead; clamp keeps u8 exact where live

// Scratch (static device globals — allocation-free per harness rules)
// g_counts[b][sc][bin]: 4 chunks' counts in the 4 byte fields (each <= 64).
__device__ unsigned int  g_counts[BB * NSC * NBINS];          // 14.7 MB
__device__ unsigned char g_off[(size_t)BB * NC * NBINS];      // 14.7 MB, clamped u8

// ---------------------------------------------------------------------------
// Kernel 1: fill output with -1.0f (118 MB, DRAM roofline-bound).
// Streaming stores (evict-first) keep L2 free for indices/g_counts/g_off.
// ---------------------------------------------------------------------------
__global__ void fill_kernel(float4* __restrict__ out) {
    int i = blockIdx.x * blockDim.x + threadIdx.x;
    float4 v = make_float4(-1.0f, -1.0f, -1.0f, -1.0f);
    int base = i * 4;
    __stcs(&out[base + 0], v);
    __stcs(&out[base + 1], v);
    __stcs(&out[base + 2], v);
    __stcs(&out[base + 3], v);
}

// ---------------------------------------------------------------------------
// Kernel 2: packed per-chunk histogram. One block (256 thr = 8 warps) per
// superchunk of 256 spikes = 4 chunks of 64. Warps 2k,2k+1 count chunk k
// into byte field k (add = 1<<(8k)). Fields never exceed 64 -> no carry.
// ---------------------------------------------------------------------------
__global__ void count_kernel(const int* __restrict__ spikes,
                             const int* __restrict__ indices) {
    __shared__ unsigned int hist[NBINS];
    int tid = threadIdx.x;
    for (int i = tid; i < NBINS; i += 256) hist[i] = 0u;
    __syncthreads();

    int b  = blockIdx.x >> 4;   // NSC == 16
    int sc = blockIdx.x & 15;
    int warp = tid >> 5, lane = tid & 31;
    const int* sp = spikes + b * SS + sc * 256 + warp * 32;
    unsigned int add = 1u << (8 * (warp >> 1));

    for (int k = 0; k < 32; k++) {
        int id = __ldg(&sp[k]);                      // uniform broadcast load
        int j = -1;
        if (lane < LL) j = __ldg(&indices[id * LL + lane]);
        if (j >= 0) {
            unsigned int bin = (unsigned int)j % (unsigned int)NBINS;
            atomicAdd(&hist[bin], add);
        }
    }
    __syncthreads();

    unsigned int* dst = g_counts + (size_t)blockIdx.x * NBINS;
    for (int i = tid; i < NBINS; i += 256) dst[i] = hist[i];
}

// ---------------------------------------------------------------------------
// Kernel 3: exclusive scan over 64 chunks per (b,bin). One thread handles 4
// CONSECUTIVE bins and composes each chunk's 4 u8 offsets into ONE u32 store
// (R5's version issued 64 byte-stores/thread -> 14.7M STG.U8, issue-bound
// ~13us; this drops total stores to 3.7M coalesced u32).
// ---------------------------------------------------------------------------
__global__ void scan_kernel() {
    int idx = blockIdx.x * 256 + threadIdx.x;       // thread per 4 bins
    if (idx >= BB * (NBINS / 4)) return;
    int b  = idx / (NBINS / 4);
    int bq = idx - b * (NBINS / 4);
    int bin0 = bq * 4;

    unsigned int s0 = 0, s1 = 0, s2 = 0, s3 = 0;
#pragma unroll
    for (int sc = 0; sc < NSC; sc++) {
        const uint4* src = (const uint4*)(g_counts
                           + ((size_t)(b * NSC + sc)) * NBINS + bin0);
        uint4 v = __ldg(src);
#pragma unroll
        for (int sub = 0; sub < 4; sub++) {
            int c = sc * 4 + sub;
            unsigned int o0 = min(s0, OFFCLAMP);
            unsigned int o1 = min(s1, OFFCLAMP);
            unsigned int o2 = min(s2, OFFCLAMP);
            unsigned int o3 = min(s3, OFFCLAMP);
            unsigned int w = o0 | (o1 << 8) | (o2 << 16) | (o3 << 24);
            *(unsigned int*)(g_off + ((size_t)(b * NC + c)) * NBINS + bin0) = w;
            unsigned int sh = 8 * sub;
            s0 += (v.x >> sh) & 0xFFu;
            s1 += (v.y >> sh) & 0xFFu;
            s2 += (v.z >> sh) & 0xFFu;
            s3 += (v.w >> sh) & 0xFFu;
        }
    }
}

// ---------------------------------------------------------------------------
// Kernel 4: ordered scatter. One WARP per (b,chunk) of 64 spikes; 4 warps per
// block, 14.4 KB u8 counters. Depth-8 software pipeline.
// Counter max = 160(clamp) + 64(chunk) = 224 < 256 -> u8 exact where live.
// Ordering: within one spike the 25 bins are distinct so lanes never collide;
// __syncwarp between spikes orders the byte RMWs across spikes.
// ---------------------------------------------------------------------------
__global__ void scatter_kernel(const int* __restrict__ spikes,
                               const int* __restrict__ indices,
                               float* __restrict__ out) {
    __shared__ __align__(16) unsigned char cnt[4 * NBINS];   // 14.4 KB
    const unsigned int FULL = 0xffffffffu;
    int warp = threadIdx.x >> 5, lane = threadIdx.x & 31;
    int chunk = blockIdx.x * 4 + warp;
    int b = chunk >> 6;        // NC == 64
    int c = chunk & 63;

    // uint4 preload of u8 counters (3600 B = 225 uint4 per warp).
    unsigned char* my = cnt + warp * NBINS;
    {
        const uint4* offv = (const uint4*)(g_off + (size_t)chunk * NBINS);
        uint4* myv = (uint4*)my;
        for (int i = lane; i < NBINS / 16; i += 32) myv[i] = __ldg(&offv[i]);
    }

    const int* sp = spikes + b * SS + c * CHUNK;
    int idlo = __ldg(&sp[lane]);        // spikes 0..31
    int idhi = __ldg(&sp[32 + lane]);   // spikes 32..63
    float* outb = out + (size_t)b * CAPC * NBINS;
    bool act = lane < LL;
    __syncwarp();

    #define GATHER(dst, s) do {                                              \
        int _id = ((s) < 32) ? __shfl_sync(FULL, idlo, (s))                  \
                             : __shfl_sync(FULL, idhi, (s) - 32);            \
        (dst) = act ? __ldg(&indices[_id * LL + lane]) : -1;                 \
    } while (0)

    #define PROCESS(jv) do {                                                 \
        if ((jv) >= 0) {                                                     \
            unsigned int ju  = (unsigned int)(jv);                           \
            unsigned int ckk = ju / (unsigned int)NBINS;                     \
            unsigned int bin = ju - ckk * (unsigned int)NBINS;               \
            unsigned int r = my[bin];                                        \
            my[bin] = (unsigned char)(r + 1u);                               \
            if (r < CAPC) outb[(size_t)r * NBINS + bin] = (float)ckk;        \
        }                                                                    \
        __syncwarp();                                                        \
    } while (0)

    int a0, a1, a2, a3, b0, b1, b2, b3;
    GATHER(a0, 0); GATHER(a1, 1); GATHER(a2, 2); GATHER(a3, 3);
    GATHER(b0, 4); GATHER(b1, 5); GATHER(b2, 6); GATHER(b3, 7);

    #pragma unroll 4
    for (int g = 0; g < CHUNK / 4 - 2; g++) {
        int s = g * 4;
        int c0, c1, c2, c3;
        GATHER(c0, s + 8); GATHER(c1, s + 9);
        GATHER(c2, s + 10); GATHER(c3, s + 11);
        PROCESS(a0); PROCESS(a1); PROCESS(a2); PROCESS(a3);
        a0 = b0; a1 = b1; a2 = b2; a3 = b3;
        b0 = c0; b1 = c1; b2 = c2; b3 = c3;
    }
    PROCESS(a0); PROCESS(a1); PROCESS(a2); PROCESS(a3);
    PROCESS(b0); PROCESS(b1); PROCESS(b2); PROCESS(b3);

    #undef GATHER
    #undef PROCESS
}

// ---------------------------------------------------------------------------
extern "C" void kernel_launch(void* const* d_in, const int* in_sizes, int n_in,
                              void* d_out, int out_size) {
    const int* spikes  = (const int*)d_in[0];   // (64, 4096, 1, 1) int32
    const int* indices = (const int*)d_in[1];   // (131072, 25) int32
    float* out = (float*)d_out;                 // (64, 128, 60, 60) float32

    fill_kernel<<<7200, 256>>>((float4*)out);
    count_kernel<<<BB * NSC, 256>>>(spikes, indices);
    scan_kernel<<<(BB * (NBINS / 4) + 255) / 256, 256>>>();
    scatter_kernel<<<BB * NC / 4, 128>>>(spikes, indices, out);
}